// round 13
// baseline (speedup 1.0000x reference)
#include <cuda_runtime.h>

// ---------------------------------------------------------------------------
// Fused 3-layer tanh RNN + FC head, single persistent time loop per CTA.
//   B=8192, T=80, D=32, H=64.  CTA = 64 batch elems, 256 threads, grid=128.
//
// v7 = v3 (760us skeleton: broadcast h LDS.128 + spread w LDS.64, separate
// input/recurrent accum loops, warp-private batch tiles, __syncwarp-only
// time loop) with ONE change: software tanhf -> tanh.approx.f32 (MUFU.TANH).
// v6 proved the accuracy is fine (rel_err 1.1e-5 << 1e-3) but its merged
// k-loop regressed scheduling; this keeps v3's loop structure untouched.
// ---------------------------------------------------------------------------

#define B_TOT    8192
#define T_STEPS  80
#define D_IN     32
#define HDIM     64
#define BT       64          // batch tile per CTA
#define NTHREADS 256
#define P        68          // smem row pitch in floats

// smem layout offsets (in floats)
#define OFF_X    0
#define OFF_H0   (OFF_X    + D_IN * P)
#define OFF_H1   (OFF_H0   + HDIM * P)
#define OFF_H2   (OFF_H1   + HDIM * P)
#define OFF_WIH0 (OFF_H2   + HDIM * P)
#define OFF_WHH0 (OFF_WIH0 + D_IN * P)
#define OFF_WIH1 (OFF_WHH0 + HDIM * P)
#define OFF_WHH1 (OFF_WIH1 + HDIM * P)
#define OFF_WIH2 (OFF_WHH1 + HDIM * P)
#define OFF_WHH2 (OFF_WIH2 + HDIM * P)
#define OFF_BS   (OFF_WHH2 + HDIM * P)   // 3 x 64 combined biases
#define OFF_WFC  (OFF_BS   + 3 * HDIM)
#define OFF_BFC  (OFF_WFC  + HDIM)
#define SMEM_FLOATS (OFF_BFC + 1)

// ---- packed fp32x2 helpers --------------------------------------------------
__device__ __forceinline__ unsigned long long dup2(float v) {
    unsigned long long r;
    asm("mov.b64 %0, {%1, %1};" : "=l"(r) : "f"(v));
    return r;
}
__device__ __forceinline__ float2 unpack2(unsigned long long v) {
    float2 r;
    asm("mov.b64 {%0, %1}, %2;" : "=f"(r.x), "=f"(r.y) : "l"(v));
    return r;
}
#define FMA2(accv, av, bv) \
    asm("fma.rn.f32x2 %0, %1, %2, %0;" : "+l"(accv) : "l"(av), "l"(bv))

// ---- fast tanh via MUFU.TANH (sm_75+); v6 measured rel_err 1.1e-5 ----------
__device__ __forceinline__ float tanh_fast(float x) {
    float y;
    asm("tanh.approx.f32 %0, %1;" : "=f"(y) : "f"(x));
    return y;
}

// ---- outer-product accumulate over K: acc[b-pair][j] += inT[k][b] * WT[k][j]
template <int K>
__device__ __forceinline__ void accum(const float* __restrict__ inT,
                                      const float* __restrict__ WT,
                                      int b0, int j0,
                                      unsigned long long acc[4][2]) {
#pragma unroll 16
    for (int k = 0; k < K; ++k) {
        double2 ha = *reinterpret_cast<const double2*>(inT + k * P + b0);
        double2 hb = *reinterpret_cast<const double2*>(inT + k * P + b0 + 4);
        float2 wv = *reinterpret_cast<const float2*>(WT + k * P + j0);
        unsigned long long w0 = dup2(wv.x);
        unsigned long long w1 = dup2(wv.y);
        unsigned long long h01 = __double_as_longlong(ha.x);
        unsigned long long h23 = __double_as_longlong(ha.y);
        unsigned long long h45 = __double_as_longlong(hb.x);
        unsigned long long h67 = __double_as_longlong(hb.y);
        FMA2(acc[0][0], h01, w0); FMA2(acc[0][1], h01, w1);
        FMA2(acc[1][0], h23, w0); FMA2(acc[1][1], h23, w1);
        FMA2(acc[2][0], h45, w0); FMA2(acc[2][1], h45, w1);
        FMA2(acc[3][0], h67, w0); FMA2(acc[3][1], h67, w1);
    }
}

// ---- one RNN layer step: h_out = tanh(bias + WinT^T in + WhhT^T h_out_prev)
// Warp-private: all smem traffic touches only this warp's batch columns.
template <int KIN>
__device__ __forceinline__ void layer_step(const float* __restrict__ inT,
                                           const float* __restrict__ WinT,
                                           float* __restrict__ hT,
                                           const float* __restrict__ WhhT,
                                           const float* __restrict__ bs,
                                           int b0, int j0) {
    unsigned long long acc[4][2];
    float2 bv = *reinterpret_cast<const float2*>(bs + j0);
#pragma unroll
    for (int i = 0; i < 4; ++i) { acc[i][0] = dup2(bv.x); acc[i][1] = dup2(bv.y); }

    accum<KIN>(inT, WinT, b0, j0, acc);   // input projection
    accum<HDIM>(hT,  WhhT, b0, j0, acc);  // recurrent part (reads old h)

    __syncwarp();  // all lanes' reads of old hT columns done before overwrite

    float2 p0 = unpack2(acc[0][0]), p1 = unpack2(acc[1][0]);
    float2 p2 = unpack2(acc[2][0]), p3 = unpack2(acc[3][0]);
    *reinterpret_cast<float4*>(hT + j0 * P + b0) =
        make_float4(tanh_fast(p0.x), tanh_fast(p0.y),
                    tanh_fast(p1.x), tanh_fast(p1.y));
    *reinterpret_cast<float4*>(hT + j0 * P + b0 + 4) =
        make_float4(tanh_fast(p2.x), tanh_fast(p2.y),
                    tanh_fast(p3.x), tanh_fast(p3.y));

    float2 q0 = unpack2(acc[0][1]), q1 = unpack2(acc[1][1]);
    float2 q2 = unpack2(acc[2][1]), q3 = unpack2(acc[3][1]);
    *reinterpret_cast<float4*>(hT + (j0 + 1) * P + b0) =
        make_float4(tanh_fast(q0.x), tanh_fast(q0.y),
                    tanh_fast(q1.x), tanh_fast(q1.y));
    *reinterpret_cast<float4*>(hT + (j0 + 1) * P + b0 + 4) =
        make_float4(tanh_fast(q2.x), tanh_fast(q2.y),
                    tanh_fast(q3.x), tanh_fast(q3.y));

    __syncwarp();  // new h visible to all lanes of this warp
}

// ---- transpose weight [64][K] row-major -> WT[k*P + j] ----------------------
__device__ __forceinline__ void load_wT(const float* __restrict__ W,
                                        float* __restrict__ WT, int K, int tid) {
    for (int idx = tid; idx < HDIM * K; idx += NTHREADS) {
        int j = idx / K;
        int k = idx - j * K;
        WT[k * P + j] = W[idx];
    }
}

__global__ void __launch_bounds__(NTHREADS, 1)
rnn_fused_v7(const float* __restrict__ x,
             const float* __restrict__ Wih0, const float* __restrict__ Whh0,
             const float* __restrict__ bih0, const float* __restrict__ bhh0,
             const float* __restrict__ Wih1, const float* __restrict__ Whh1,
             const float* __restrict__ bih1, const float* __restrict__ bhh1,
             const float* __restrict__ Wih2, const float* __restrict__ Whh2,
             const float* __restrict__ bih2, const float* __restrict__ bhh2,
             const float* __restrict__ Wfc,  const float* __restrict__ bfc,
             float* __restrict__ out) {
    extern __shared__ float smem[];
    const int tid   = threadIdx.x;
    const int bbase = blockIdx.x * BT;

    // ---- one-time setup: weights (transposed), biases, zero hidden states
    load_wT(Wih0, smem + OFF_WIH0, D_IN, tid);
    load_wT(Whh0, smem + OFF_WHH0, HDIM, tid);
    load_wT(Wih1, smem + OFF_WIH1, HDIM, tid);
    load_wT(Whh1, smem + OFF_WHH1, HDIM, tid);
    load_wT(Wih2, smem + OFF_WIH2, HDIM, tid);
    load_wT(Whh2, smem + OFF_WHH2, HDIM, tid);
    if (tid < 3 * HDIM) {
        int l = tid >> 6, j = tid & 63;
        const float* bi = (l == 0) ? bih0 : (l == 1) ? bih1 : bih2;
        const float* bh = (l == 0) ? bhh0 : (l == 1) ? bhh1 : bhh2;
        smem[OFF_BS + tid] = bi[j] + bh[j];
    }
    if (tid < HDIM) smem[OFF_WFC + tid] = Wfc[tid];
    if (tid == 0)   smem[OFF_BFC] = bfc[0];
    for (int i = tid; i < 3 * HDIM * P; i += NTHREADS) smem[OFF_H0 + i] = 0.0f;

    // ---- x prefetch: each thread owns 8 consecutive floats of one row
    // (warp-private: warp w's threads cover exactly batch columns w*8..w*8+7)
    const int xb = tid >> 2;            // local batch index 0..63
    const int xd = (tid & 3) * 8;       // d offset 0,8,16,24
    const float* xp = x + (size_t)(bbase + xb) * (T_STEPS * D_IN) + xd;
    float4 xr0 = *reinterpret_cast<const float4*>(xp);
    float4 xr1 = *reinterpret_cast<const float4*>(xp + 4);

    __syncthreads();   // weights/biases/zeroed state visible to all warps

    const int lane = tid & 31;
    const int b0   = (tid >> 5) * 8;    // warp's batch sub-tile
    const int j0   = lane * 2;          // lane's hidden-unit pair

    for (int t = 0; t < T_STEPS; ++t) {
        // stage x_t into smem (transposed: xT[d][b]); prefetch x_{t+1}
        float* xc = smem + OFF_X + xb;
        xc[(xd + 0) * P] = xr0.x; xc[(xd + 1) * P] = xr0.y;
        xc[(xd + 2) * P] = xr0.z; xc[(xd + 3) * P] = xr0.w;
        xc[(xd + 4) * P] = xr1.x; xc[(xd + 5) * P] = xr1.y;
        xc[(xd + 6) * P] = xr1.z; xc[(xd + 7) * P] = xr1.w;
        if (t + 1 < T_STEPS) {
            xr0 = *reinterpret_cast<const float4*>(xp + (t + 1) * D_IN);
            xr1 = *reinterpret_cast<const float4*>(xp + (t + 1) * D_IN + 4);
        }
        __syncwarp();   // warp's x columns staged

        layer_step<D_IN>(smem + OFF_X,  smem + OFF_WIH0, smem + OFF_H0,
                         smem + OFF_WHH0, smem + OFF_BS,            b0, j0);
        layer_step<HDIM>(smem + OFF_H0, smem + OFF_WIH1, smem + OFF_H1,
                         smem + OFF_WHH1, smem + OFF_BS + HDIM,     b0, j0);
        layer_step<HDIM>(smem + OFF_H1, smem + OFF_WIH2, smem + OFF_H2,
                         smem + OFF_WHH2, smem + OFF_BS + 2 * HDIM, b0, j0);
    }

    __syncthreads();   // FC head reads h2 across warp boundaries

    // ---- FC head: out[b] = h2_last[b] . Wfc + bfc (exact fp32 math) --------
    if (tid < BT) {
        float s = smem[OFF_BFC];
        const float* h2 = smem + OFF_H2;
        const float* wf = smem + OFF_WFC;
#pragma unroll
        for (int j = 0; j < HDIM; ++j) s += h2[j * P + tid] * wf[j];
        out[bbase + tid] = s;
    }
}

extern "C" void kernel_launch(void* const* d_in, const int* in_sizes, int n_in,
                              void* d_out, int out_size) {
    (void)in_sizes; (void)n_in; (void)out_size;
    const size_t smem_bytes = SMEM_FLOATS * sizeof(float);
    cudaFuncSetAttribute(rnn_fused_v7,
                         cudaFuncAttributeMaxDynamicSharedMemorySize,
                         (int)smem_bytes);
    rnn_fused_v7<<<B_TOT / BT, NTHREADS, smem_bytes>>>(
        (const float*)d_in[0],
        (const float*)d_in[1],  (const float*)d_in[2],
        (const float*)d_in[3],  (const float*)d_in[4],
        (const float*)d_in[5],  (const float*)d_in[6],
        (const float*)d_in[7],  (const float*)d_in[8],
        (const float*)d_in[9],  (const float*)d_in[10],
        (const float*)d_in[11], (const float*)d_in[12],
        (const float*)d_in[13], (const float*)d_in[14],
        (float*)d_out);
}

// round 15
// speedup vs baseline: 2.3195x; 2.3195x over previous
#include <cuda_runtime.h>

typedef unsigned int u32; typedef unsigned long long u64; typedef unsigned short u16;

#define B_TOT   8192
#define T_STEPS 80
#define BT      64
#define NTH     256

#define PX 80     // x row pitch bytes (40 bf16)
#define PH 144    // h row pitch bytes (72 bf16)
#define SM_XHI  0
#define SM_XLO  5120
#define SM_H0HI 10240
#define SM_H0LO 19456
#define SM_H1HI 28672
#define SM_H1LO 37888
#define SM_H2HI 47104
#define SM_H2LO 56320
#define SM_BIAS 65536
#define SM_WFC  66304
#define SM_BFC  66560
#define SMEM_BYTES 66816

__device__ __forceinline__ u32 s2u(const void* p) {
    u32 a;
    asm("{ .reg .u64 t; cvta.to.shared.u64 t, %1; cvt.u32.u64 %0, t; }" : "=r"(a) : "l"(p));
    return a;
}
__device__ __forceinline__ float tf(float x) {
    float y; asm("tanh.approx.f32 %0, %1;" : "=f"(y) : "f"(x)); return y;
}
// pack {low half = a, high half = b} as bf16x2
__device__ __forceinline__ u32 p2(float a, float b) {
    u32 r; asm("cvt.rn.bf16x2.f32 %0, %1, %2;" : "=r"(r) : "f"(b), "f"(a)); return r;
}
__device__ __forceinline__ float blo(u32 p) { return __uint_as_float(p << 16); }
__device__ __forceinline__ float bhi(u32 p) { return __uint_as_float(p & 0xffff0000u); }

#define LDSM4(d, a) \
    asm volatile("ldmatrix.sync.aligned.m8n8.x4.shared.b16 {%0,%1,%2,%3}, [%4];" \
        : "=r"((d)[0]), "=r"((d)[1]), "=r"((d)[2]), "=r"((d)[3]) : "r"(a))
#define MMA(c, a, b) \
    asm volatile("mma.sync.aligned.m16n8k16.row.col.f32.bf16.bf16.f32 " \
        "{%0,%1,%2,%3},{%4,%5,%6,%7},{%8,%9},{%0,%1,%2,%3};" \
        : "+f"((c)[0]), "+f"((c)[1]), "+f"((c)[2]), "+f"((c)[3]) \
        : "r"((a)[0]), "r"((a)[1]), "r"((a)[2]), "r"((a)[3]), "r"((b)[0]), "r"((b)[1]))

// build b-frags (col-major B = W[j][k], n=g, k pairs tig*2 / +8) hi+lo split
#define MKB(W, K, BASE, NCH) do { \
    _Pragma("unroll") for (int ch = 0; ch < (NCH); ++ch) \
    _Pragma("unroll") for (int r = 0; r < 2; ++r) { \
        int k_ = ch * 16 + tig * 2 + r * 8; \
        float w0_ = (W)[j * (K) + k_], w1_ = (W)[j * (K) + k_ + 1]; \
        u32 ph_ = p2(w0_, w1_); \
        bH[(BASE) + ch][r] = ph_; \
        bL[(BASE) + ch][r] = p2(w0_ - blo(ph_), w1_ - bhi(ph_)); \
    } \
} while (0)

// one RNN layer: D[64b][8j/warp] = in*Win + self*Whh (+bias), tanh, split-store
template <int NIN, int BIN, int BSELF, int PIN>
__device__ __forceinline__ void layer(u32 inHi, u32 inLo, u32 selfHi, u32 selfLo,
                                      char* sm, u32 sb,
                                      const u32 bH[22][2], const u32 bL[22][2],
                                      float be, float bo,
                                      int r0, int k0, int g, int tig, int warp) {
    float c[4][4];
#pragma unroll
    for (int mt = 0; mt < 4; ++mt) { c[mt][0] = be; c[mt][1] = bo; c[mt][2] = be; c[mt][3] = bo; }
#pragma unroll
    for (int ch = 0; ch < NIN; ++ch)
#pragma unroll
        for (int mt = 0; mt < 4; ++mt) {
            u32 aH[4], aL[4];
            u32 ad = inHi + (u32)((mt * 16 + r0) * PIN + ch * 32 + k0 * 2);
            LDSM4(aH, ad); LDSM4(aL, ad + (inLo - inHi));
            MMA(c[mt], aH, bH[BIN + ch]);
            MMA(c[mt], aL, bH[BIN + ch]);
            MMA(c[mt], aH, bL[BIN + ch]);
        }
#pragma unroll
    for (int ch = 0; ch < 4; ++ch)
#pragma unroll
        for (int mt = 0; mt < 4; ++mt) {
            u32 aH[4], aL[4];
            u32 ad = selfHi + (u32)((mt * 16 + r0) * PH + ch * 32 + k0 * 2);
            LDSM4(aH, ad); LDSM4(aL, ad + (selfLo - selfHi));
            MMA(c[mt], aH, bH[BSELF + ch]);
            MMA(c[mt], aL, bH[BSELF + ch]);
            MMA(c[mt], aH, bL[BSELF + ch]);
        }
    __syncthreads();   // all reads of self (old h) done before overwrite
    const int cb = (warp * 8 + tig * 2) * 2;
    char* sHi = sm + (selfHi - sb);
    char* sLo = sm + (selfLo - sb);
#pragma unroll
    for (int mt = 0; mt < 4; ++mt) {
        float e0 = tf(c[mt][0]), e1 = tf(c[mt][1]), e2 = tf(c[mt][2]), e3 = tf(c[mt][3]);
        u32 pa = p2(e0, e1), pb = p2(e2, e3);
        u32 la = p2(e0 - blo(pa), e1 - bhi(pa));
        u32 lb = p2(e2 - blo(pb), e3 - bhi(pb));
        int ra = (mt * 16 + g) * PH + cb, rb = (mt * 16 + 8 + g) * PH + cb;
        *(u32*)(sHi + ra) = pa;
        *(u32*)(sHi + rb) = pb;
        *(u32*)(sLo + ra) = la;
        *(u32*)(sLo + rb) = lb;
    }
    __syncthreads();   // new h visible
}

__global__ void __launch_bounds__(NTH, 1)
rnn_mma_v9(const float* __restrict__ x,
           const float* __restrict__ Wih0, const float* __restrict__ Whh0,
           const float* __restrict__ bih0, const float* __restrict__ bhh0,
           const float* __restrict__ Wih1, const float* __restrict__ Whh1,
           const float* __restrict__ bih1, const float* __restrict__ bhh1,
           const float* __restrict__ Wih2, const float* __restrict__ Whh2,
           const float* __restrict__ bih2, const float* __restrict__ bhh2,
           const float* __restrict__ Wfc,  const float* __restrict__ bfc,
           float* __restrict__ out) {
    extern __shared__ __align__(16) char sm[];
    const int tid = threadIdx.x, warp = tid >> 5, lane = tid & 31;
    const int g = lane >> 2, tig = lane & 3;
    const int r0 = (lane & 7) + ((lane >> 3) & 1) * 8;   // ldmatrix row in m16 tile
    const int k0 = ((lane >> 4) & 1) * 8;                // ldmatrix k-offset (elems)
    const u32 sb = s2u(sm);
    const int bbase = blockIdx.x * BT;

    // zero x + h regions
    for (int i = tid; i < SM_BIAS / 8; i += NTH) ((u64*)sm)[i] = 0ULL;
    if (tid < 192) {
        int l = tid >> 6, jj = tid & 63;
        const float* bi = (l == 0) ? bih0 : (l == 1) ? bih1 : bih2;
        const float* bh_ = (l == 0) ? bhh0 : (l == 1) ? bhh1 : bhh2;
        ((float*)(sm + SM_BIAS))[tid] = bi[jj] + bh_[jj];
    }
    if (tid < 64) ((float*)(sm + SM_WFC))[tid] = Wfc[tid];
    if (tid == 0) ((float*)(sm + SM_BFC))[0] = bfc[0];

    // B-fragments (weights) resident in registers, hi+lo split
    u32 bH[22][2], bL[22][2];
    const int j = warp * 8 + g;
    MKB(Wih0, 32, 0, 2);  MKB(Whh0, 64, 2, 4);
    MKB(Wih1, 64, 6, 4);  MKB(Whh1, 64, 10, 4);
    MKB(Wih2, 64, 14, 4); MKB(Whh2, 64, 18, 4);

    __syncthreads();
    const float* bias = (const float*)(sm + SM_BIAS);
    const int bj = warp * 8 + tig * 2;
    float be0 = bias[bj],       bo0 = bias[bj + 1];
    float be1 = bias[64 + bj],  bo1 = bias[64 + bj + 1];
    float be2 = bias[128 + bj], bo2 = bias[128 + bj + 1];

    // x prefetch: threads 0..63, one batch row each
    const float* xp = x + (size_t)(bbase + tid) * (T_STEPS * 32);
    float4 xr[8];
    if (tid < 64) {
#pragma unroll
        for (int i = 0; i < 8; ++i) xr[i] = ((const float4*)xp)[i];
    }

    for (int t = 0; t < T_STEPS; ++t) {
        if (tid < 64) {
            float xv[32];
#pragma unroll
            for (int i = 0; i < 8; ++i) ((float4*)xv)[i] = xr[i];
            u32 xh[16], xl[16];
#pragma unroll
            for (int i = 0; i < 16; ++i) {
                float a = xv[2 * i], b = xv[2 * i + 1];
                u32 p = p2(a, b);
                xh[i] = p;
                xl[i] = p2(a - blo(p), b - bhi(p));
            }
            char* rp = sm + SM_XHI + tid * PX;
#pragma unroll
            for (int i = 0; i < 4; ++i) ((uint4*)rp)[i] = ((uint4*)xh)[i];
            rp = sm + SM_XLO + tid * PX;
#pragma unroll
            for (int i = 0; i < 4; ++i) ((uint4*)rp)[i] = ((uint4*)xl)[i];
            if (t + 1 < T_STEPS) {
                const float4* xn = (const float4*)(xp + (t + 1) * 32);
#pragma unroll
                for (int i = 0; i < 8; ++i) xr[i] = xn[i];
            }
        }
        __syncthreads();

        layer<2, 0, 2, PX>(sb + SM_XHI, sb + SM_XLO, sb + SM_H0HI, sb + SM_H0LO,
                           sm, sb, bH, bL, be0, bo0, r0, k0, g, tig, warp);
        layer<4, 6, 10, PH>(sb + SM_H0HI, sb + SM_H0LO, sb + SM_H1HI, sb + SM_H1LO,
                            sm, sb, bH, bL, be1, bo1, r0, k0, g, tig, warp);
        layer<4, 14, 18, PH>(sb + SM_H1HI, sb + SM_H1LO, sb + SM_H2HI, sb + SM_H2LO,
                             sm, sb, bH, bL, be2, bo2, r0, k0, g, tig, warp);
    }

    // FC head from h2 (hi+lo reconstruct)
    if (tid < 64) {
        float s = ((const float*)(sm + SM_BFC))[0];
        const float* wf = (const float*)(sm + SM_WFC);
#pragma unroll
        for (int jj = 0; jj < 64; ++jj) {
            u16 hb = *(const u16*)(sm + SM_H2HI + tid * PH + jj * 2);
            u16 lb = *(const u16*)(sm + SM_H2LO + tid * PH + jj * 2);
            float hv = __uint_as_float(((u32)hb) << 16) + __uint_as_float(((u32)lb) << 16);
            s += hv * wf[jj];
        }
        out[bbase + tid] = s;
    }
}

extern "C" void kernel_launch(void* const* d_in, const int* in_sizes, int n_in,
                              void* d_out, int out_size) {
    (void)in_sizes; (void)n_in; (void)out_size;
    cudaFuncSetAttribute(rnn_mma_v9,
                         cudaFuncAttributeMaxDynamicSharedMemorySize, SMEM_BYTES);
    rnn_mma_v9<<<B_TOT / BT, NTH, SMEM_BYTES>>>(
        (const float*)d_in[0],
        (const float*)d_in[1],  (const float*)d_in[2],
        (const float*)d_in[3],  (const float*)d_in[4],
        (const float*)d_in[5],  (const float*)d_in[6],
        (const float*)d_in[7],  (const float*)d_in[8],
        (const float*)d_in[9],  (const float*)d_in[10],
        (const float*)d_in[11], (const float*)d_in[12],
        (const float*)d_in[13], (const float*)d_in[14],
        (float*)d_out);
}

// round 17
// speedup vs baseline: 3.7346x; 1.6101x over previous
#include <cuda_runtime.h>
#include <cuda_fp16.h>

typedef unsigned int u32; typedef unsigned long long u64; typedef unsigned short u16;

#define B_TOT   8192
#define T_STEPS 80
#define BT      64
#define NTH     256

#define PX 80     // x row pitch bytes (32 fp16 + pad)
#define PH 144    // h row pitch bytes (64 fp16 + pad)
#define SM_X    0
#define SM_H0   5120
#define SM_H1   14336
#define SM_H2   23552
#define SM_BIAS 32768
#define SM_WFC  33536
#define SM_BFC  33792
#define SMEM_BYTES 34048

__device__ __forceinline__ u32 s2u(const void* p) {
    u32 a;
    asm("{ .reg .u64 t; cvta.to.shared.u64 t, %1; cvt.u32.u64 %0, t; }" : "=r"(a) : "l"(p));
    return a;
}
__device__ __forceinline__ float tf(float x) {
    float y; asm("tanh.approx.f32 %0, %1;" : "=f"(y) : "f"(x)); return y;
}
// pack {lo half = a, hi half = b} as fp16x2
__device__ __forceinline__ u32 pkh(float a, float b) {
    __half2 v = __floats2half2_rn(a, b);
    return *reinterpret_cast<u32*>(&v);
}
__device__ __forceinline__ float hlo(u32 p) {
    __half2 v = *reinterpret_cast<__half2*>(&p); return __low2float(v);
}
__device__ __forceinline__ float hhi(u32 p) {
    __half2 v = *reinterpret_cast<__half2*>(&p); return __high2float(v);
}

#define LDSM4(d, a) \
    asm volatile("ldmatrix.sync.aligned.m8n8.x4.shared.b16 {%0,%1,%2,%3}, [%4];" \
        : "=r"((d)[0]), "=r"((d)[1]), "=r"((d)[2]), "=r"((d)[3]) : "r"(a))
#define MMA(c, a, b) \
    asm volatile("mma.sync.aligned.m16n8k16.row.col.f32.f16.f16.f32 " \
        "{%0,%1,%2,%3},{%4,%5,%6,%7},{%8,%9},{%0,%1,%2,%3};" \
        : "+f"((c)[0]), "+f"((c)[1]), "+f"((c)[2]), "+f"((c)[3]) \
        : "r"((a)[0]), "r"((a)[1]), "r"((a)[2]), "r"((a)[3]), "r"((b)[0]), "r"((b)[1]))

// build b-frags (col-major B = W[j][k]) with fp16 hi/lo weight split
#define MKB(W, K, BASE, NCH) do { \
    _Pragma("unroll") for (int ch = 0; ch < (NCH); ++ch) \
    _Pragma("unroll") for (int r = 0; r < 2; ++r) { \
        int k_ = ch * 16 + tig * 2 + r * 8; \
        float w0_ = (W)[j * (K) + k_], w1_ = (W)[j * (K) + k_ + 1]; \
        u32 ph_ = pkh(w0_, w1_); \
        bH[(BASE) + ch][r] = ph_; \
        bL[(BASE) + ch][r] = pkh(w0_ - hlo(ph_), w1_ - hhi(ph_)); \
    } \
} while (0)

// one RNN layer: D[64b][8j/warp] = in*Win + self*Whh (+bias), tanh, fp16 store
template <int NIN, int BIN, int BSELF, int PIN>
__device__ __forceinline__ void layer(u32 inA, u32 selfA, char* sm, u32 sb,
                                      const u32 bH[22][2], const u32 bL[22][2],
                                      float be, float bo,
                                      int r0, int k0, int g, int tig, int warp) {
    float c[4][4];
#pragma unroll
    for (int mt = 0; mt < 4; ++mt) { c[mt][0] = be; c[mt][1] = bo; c[mt][2] = be; c[mt][3] = bo; }
#pragma unroll
    for (int ch = 0; ch < NIN; ++ch)
#pragma unroll
        for (int mt = 0; mt < 4; ++mt) {
            u32 aH[4];
            LDSM4(aH, inA + (u32)((mt * 16 + r0) * PIN + ch * 32 + k0 * 2));
            MMA(c[mt], aH, bH[BIN + ch]);
            MMA(c[mt], aH, bL[BIN + ch]);
        }
#pragma unroll
    for (int ch = 0; ch < 4; ++ch)
#pragma unroll
        for (int mt = 0; mt < 4; ++mt) {
            u32 aH[4];
            LDSM4(aH, selfA + (u32)((mt * 16 + r0) * PH + ch * 32 + k0 * 2));
            MMA(c[mt], aH, bH[BSELF + ch]);
            MMA(c[mt], aH, bL[BSELF + ch]);
        }
    __syncthreads();   // all reads of self (old h) done before overwrite
    const int cb = (warp * 8 + tig * 2) * 2;
    char* sH = sm + (selfA - sb);
#pragma unroll
    for (int mt = 0; mt < 4; ++mt) {
        float e0 = tf(c[mt][0]), e1 = tf(c[mt][1]), e2 = tf(c[mt][2]), e3 = tf(c[mt][3]);
        *(u32*)(sH + (mt * 16 + g) * PH + cb)     = pkh(e0, e1);
        *(u32*)(sH + (mt * 16 + 8 + g) * PH + cb) = pkh(e2, e3);
    }
    __syncthreads();   // new h visible
}

__global__ void __launch_bounds__(NTH, 1)
rnn_mma_v10(const float* __restrict__ x,
            const float* __restrict__ Wih0, const float* __restrict__ Whh0,
            const float* __restrict__ bih0, const float* __restrict__ bhh0,
            const float* __restrict__ Wih1, const float* __restrict__ Whh1,
            const float* __restrict__ bih1, const float* __restrict__ bhh1,
            const float* __restrict__ Wih2, const float* __restrict__ Whh2,
            const float* __restrict__ bih2, const float* __restrict__ bhh2,
            const float* __restrict__ Wfc,  const float* __restrict__ bfc,
            float* __restrict__ out) {
    extern __shared__ __align__(16) char sm[];
    const int tid = threadIdx.x, warp = tid >> 5, lane = tid & 31;
    const int g = lane >> 2, tig = lane & 3;
    const int r0 = (lane & 7) + ((lane >> 3) & 1) * 8;   // ldmatrix row in m16 tile
    const int k0 = ((lane >> 4) & 1) * 8;                // ldmatrix k-offset (elems)
    const u32 sb = s2u(sm);
    const int bbase = blockIdx.x * BT;

    // zero x + h regions
    for (int i = tid; i < SM_BIAS / 8; i += NTH) ((u64*)sm)[i] = 0ULL;
    if (tid < 192) {
        int l = tid >> 6, jj = tid & 63;
        const float* bi = (l == 0) ? bih0 : (l == 1) ? bih1 : bih2;
        const float* bh_ = (l == 0) ? bhh0 : (l == 1) ? bhh1 : bhh2;
        ((float*)(sm + SM_BIAS))[tid] = bi[jj] + bh_[jj];
    }
    if (tid < 64) ((float*)(sm + SM_WFC))[tid] = Wfc[tid];
    if (tid == 0) ((float*)(sm + SM_BFC))[0] = bfc[0];

    // B-fragments (weights) resident in registers, fp16 hi+lo split
    u32 bH[22][2], bL[22][2];
    const int j = warp * 8 + g;
    MKB(Wih0, 32, 0, 2);  MKB(Whh0, 64, 2, 4);
    MKB(Wih1, 64, 6, 4);  MKB(Whh1, 64, 10, 4);
    MKB(Wih2, 64, 14, 4); MKB(Whh2, 64, 18, 4);

    __syncthreads();
    const float* bias = (const float*)(sm + SM_BIAS);
    const int bj = warp * 8 + tig * 2;
    float be0 = bias[bj],       bo0 = bias[bj + 1];
    float be1 = bias[64 + bj],  bo1 = bias[64 + bj + 1];
    float be2 = bias[128 + bj], bo2 = bias[128 + bj + 1];

    // x prefetch: threads 0..63, one batch row each
    const float* xp = x + (size_t)(bbase + tid) * (T_STEPS * 32);
    float4 xr[8];
    if (tid < 64) {
#pragma unroll
        for (int i = 0; i < 8; ++i) xr[i] = ((const float4*)xp)[i];
    }

    for (int t = 0; t < T_STEPS; ++t) {
        if (tid < 64) {
            float xv[32];
#pragma unroll
            for (int i = 0; i < 8; ++i) ((float4*)xv)[i] = xr[i];
            u32 xh[16];
#pragma unroll
            for (int i = 0; i < 16; ++i) xh[i] = pkh(xv[2 * i], xv[2 * i + 1]);
            char* rp = sm + SM_X + tid * PX;
#pragma unroll
            for (int i = 0; i < 4; ++i) ((uint4*)rp)[i] = ((uint4*)xh)[i];
            if (t + 1 < T_STEPS) {
                const float4* xn = (const float4*)(xp + (t + 1) * 32);
#pragma unroll
                for (int i = 0; i < 8; ++i) xr[i] = xn[i];
            }
        }
        __syncthreads();

        layer<2, 0, 2, PX>(sb + SM_X, sb + SM_H0, sm, sb, bH, bL, be0, bo0,
                           r0, k0, g, tig, warp);
        layer<4, 6, 10, PH>(sb + SM_H0, sb + SM_H1, sm, sb, bH, bL, be1, bo1,
                            r0, k0, g, tig, warp);
        layer<4, 14, 18, PH>(sb + SM_H1, sb + SM_H2, sm, sb, bH, bL, be2, bo2,
                             r0, k0, g, tig, warp);
    }

    // FC head from h2 (fp16 -> fp32)
    if (tid < 64) {
        float s = ((const float*)(sm + SM_BFC))[0];
        const float* wf = (const float*)(sm + SM_WFC);
#pragma unroll
        for (int jj = 0; jj < 64; ++jj) {
            u16 hb = *(const u16*)(sm + SM_H2 + tid * PH + jj * 2);
            s += __half2float(__ushort_as_half(hb)) * wf[jj];
        }
        out[bbase + tid] = s;
    }
}

extern "C" void kernel_launch(void* const* d_in, const int* in_sizes, int n_in,
                              void* d_out, int out_size) {
    (void)in_sizes; (void)n_in; (void)out_size;
    cudaFuncSetAttribute(rnn_mma_v10,
                         cudaFuncAttributeMaxDynamicSharedMemorySize, SMEM_BYTES);
    rnn_mma_v10<<<B_TOT / BT, NTH, SMEM_BYTES>>>(
        (const float*)d_in[0],
        (const float*)d_in[1],  (const float*)d_in[2],
        (const float*)d_in[3],  (const float*)d_in[4],
        (const float*)d_in[5],  (const float*)d_in[6],
        (const float*)d_in[7],  (const float*)d_in[8],
        (const float*)d_in[9],  (const float*)d_in[10],
        (const float*)d_in[11], (const float*)d_in[12],
        (const float*)d_in[13], (const float*)d_in[14],
        (float*)d_out);
}